// round 13
// baseline (speedup 1.0000x reference)
#include <cuda_runtime.h>
#include <cstdint>

// HashGrid2D: out[i] = table[bitmix_hash(floor(pos[i].x), floor(pos[i].y))]
// HASH_BITS=19, DIM=8, CELL_SIZE=1.0
//
// R10 structure (compiler-scheduled batching -- hand-pinned asm in R11 was a
// regression), with G=16 for more independent gathers per thread and .cg on
// the gather stream (L1 hit rate ~1.4% on a 16MB random working set; skip L1
// fill work). Pair-cooperative gather: 2 threads per 32B row -> adjacent
// lanes coalesce into one LDG.128 wavefront + one L2 sector per row.
//
// inputs: d_in[0] = positions [N,2] fp32, d_in[1] = table [2^19, 8] fp32
// output: [N, 8] fp32

#define HASH_BITS 19
#define HASH_MASK ((1u << HASH_BITS) - 1u)
#define G 16

__device__ __forceinline__ unsigned bitmix19(float px, float py)
{
    long long ix = (long long)floorf(px);   // CELL_SIZE = 1.0
    long long iy = (long long)floorf(py);
    long long h = ix;
    h ^= h >> 16;                           // arithmetic shift == jnp int64
    h *= 2246822507LL;
    h ^= h >> 13;
    h += iy * 3266489909LL;
    h ^= h >> 16;
    return (unsigned)h & HASH_MASK;         // mod 2^19, nonneg
}

// Fast path: n2 divisible by G*256 (N = 2^23 here -> T = 2^20, grid = 4096).
__global__ __launch_bounds__(256)
void hashgrid2d_g16_kernel(const float2* __restrict__ pos,
                           const float4* __restrict__ table,  // rows = 2x float4
                           float4* __restrict__ out,
                           int T)                              // threads = n2/G
{
    int t = blockIdx.x * blockDim.x + threadIdx.x;
    int half = t & 1;   // loop-invariant: j*T is even (T = 2^20)

    // ---- phase 1: batched streaming position loads (coalesced, pair-bcast)
    float2 p[G];
#pragma unroll
    for (int j = 0; j < G; j++)
        p[j] = __ldcs(&pos[(t + j * T) >> 1]);

    // ---- phase 2: hashes (cheap ALU under the outstanding loads)
    unsigned idx[G];
#pragma unroll
    for (int j = 0; j < G; j++)
        idx[j] = bitmix19(p[j].x, p[j].y);

    // ---- phase 3+4: gathers (.cg: bypass L1 storage, table lives in L2)
    //                 and streaming stores; ptxas picks the pipeline depth.
    float4 v[G];
#pragma unroll
    for (int j = 0; j < G; j++)
        v[j] = __ldcg(&table[((size_t)idx[j] << 1) + half]);

#pragma unroll
    for (int j = 0; j < G; j++)
        __stcs(&out[t + j * T], v[j]);
}

// Generic fallback (any N): one slot per thread, pair-cooperative.
__global__ __launch_bounds__(256)
void hashgrid2d_pair_kernel(const float2* __restrict__ pos,
                            const float4* __restrict__ table,
                            float4* __restrict__ out,
                            int n2)
{
    int t = blockIdx.x * blockDim.x + threadIdx.x;
    if (t >= n2) return;
    float2 p = pos[t >> 1];
    unsigned idx = bitmix19(p.x, p.y);
    out[t] = table[((size_t)idx << 1) + (t & 1)];
}

extern "C" void kernel_launch(void* const* d_in, const int* in_sizes, int n_in,
                              void* d_out, int out_size)
{
    const float2* pos   = (const float2*)d_in[0];
    const float4* table = (const float4*)d_in[1];
    float4*       out   = (float4*)d_out;

    int n  = in_sizes[0] / 2;   // N positions
    int n2 = n * 2;             // pair slots

    int threads = 256;
    if (n2 % (G * threads) == 0) {
        int T = n2 / G;
        hashgrid2d_g16_kernel<<<T / threads, threads>>>(pos, table, out, T);
    } else {
        hashgrid2d_pair_kernel<<<(n2 + threads - 1) / threads, threads>>>(pos, table, out, n2);
    }
}

// round 14
// speedup vs baseline: 1.2818x; 1.2818x over previous
#include <cuda_runtime.h>
#include <cstdint>

// HashGrid2D: out[i] = table[bitmix_hash(floor(pos[i].x), floor(pos[i].y))]
// HASH_BITS=19, DIM=8, CELL_SIZE=1.0
//
// Structure of the R10 winner (G=8, compiler-scheduled batching,
// pair-cooperative gather: 2 threads per 32B row -> adjacent lanes coalesce
// into one LDG.128 wavefront + one L2 sector per row), hardened with
// __launch_bounds__(256, 8) to contract regs<=32 / full occupancy (the G=16
// regs=80/occ=32% collapse in R13 is the failure mode this prevents), and
// .cg on the gather stream (L1 hit rate ~1.4% on 16MB random working set;
// skip L1 fill work, table stays L2-resident).
//
// inputs: d_in[0] = positions [N,2] fp32, d_in[1] = table [2^19, 8] fp32
// output: [N, 8] fp32

#define HASH_BITS 19
#define HASH_MASK ((1u << HASH_BITS) - 1u)
#define G 8

__device__ __forceinline__ unsigned bitmix19(float px, float py)
{
    long long ix = (long long)floorf(px);   // CELL_SIZE = 1.0
    long long iy = (long long)floorf(py);
    long long h = ix;
    h ^= h >> 16;                           // arithmetic shift == jnp int64
    h *= 2246822507LL;
    h ^= h >> 13;
    h += iy * 3266489909LL;
    h ^= h >> 16;
    return (unsigned)h & HASH_MASK;         // mod 2^19, nonneg
}

template<bool GUARD>
__global__ __launch_bounds__(256, 8)        // <=32 regs: protect occupancy
void hashgrid2d_g8_kernel(const float2* __restrict__ pos,
                          const float4* __restrict__ table,  // rows = 2x float4
                          float4* __restrict__ out,
                          int n2,                             // = 2*N slots
                          int T)                              // threads
{
    int t = blockIdx.x * blockDim.x + threadIdx.x;
    if (GUARD && t >= T) return;

    // ---- phase 1: batched streaming position loads (coalesced, pair-bcast)
    float2 p[G];
#pragma unroll
    for (int j = 0; j < G; j++) {
        int s = t + j * T;
        if (!GUARD || s < n2) p[j] = __ldcs(&pos[s >> 1]);
        else                  p[j] = make_float2(0.f, 0.f);
    }

    // ---- phase 2: hashes (int64 wraparound, matches jnp int64 semantics)
    unsigned idx[G];
#pragma unroll
    for (int j = 0; j < G; j++)
        idx[j] = bitmix19(p[j].x, p[j].y);

    // ---- phase 3: gathers, .cg = bypass L1 storage (random 16MB working
    //               set cannot hit a 228KB L1; table stays in L2)
    float4 v[G];
#pragma unroll
    for (int j = 0; j < G; j++) {
        int s = t + j * T;
        if (!GUARD || s < n2)
            v[j] = __ldcg(&table[((size_t)idx[j] << 1) + (s & 1)]);
    }

    // ---- phase 4: coalesced streaming stores (evict-first: protect table L2)
#pragma unroll
    for (int j = 0; j < G; j++) {
        int s = t + j * T;
        if (!GUARD || s < n2)
            __stcs(&out[s], v[j]);
    }
}

extern "C" void kernel_launch(void* const* d_in, const int* in_sizes, int n_in,
                              void* d_out, int out_size)
{
    const float2* pos   = (const float2*)d_in[0];
    const float4* table = (const float4*)d_in[1];
    float4*       out   = (float4*)d_out;

    int n  = in_sizes[0] / 2;   // N positions
    int n2 = n * 2;             // pair slots
    int T  = (n2 + G - 1) / G;  // threads

    int threads = 256;
    int blocks  = (T + threads - 1) / threads;

    if (n2 % G == 0) {
        hashgrid2d_g8_kernel<false><<<blocks, threads>>>(pos, table, out, n2, T);
    } else {
        hashgrid2d_g8_kernel<true><<<blocks, threads>>>(pos, table, out, n2, T);
    }
}